// round 5
// baseline (speedup 1.0000x reference)
#include <cuda_runtime.h>
#include <math.h>

#define B_  2
#define NFC 64
#define Hh  256
#define Ww  256
#define HW  (Hh*Ww)
#define DGC 8
#define CGC 8
#define KK  9
#define OMC 216
#define OM_CIN 66
#define OM_OUT 72
#define C1_CIN 128

// Scratch (static device arrays; no runtime allocation)
__device__ float g_warp[(size_t)B_*NFC*HW];   // 33.5 MB
__device__ float g_fea [(size_t)B_*NFC*HW];   // 33.5 MB
__device__ float g_om  [(size_t)B_*OMC*HW];   // 113 MB

// ---- packed f32x2 helpers (Blackwell full-rate fp32 path) ---------------
__device__ __forceinline__ void ffma2(unsigned long long& acc,
                                      unsigned long long a,
                                      unsigned long long b) {
    asm("fma.rn.f32x2 %0, %1, %2, %0;" : "+l"(acc) : "l"(a), "l"(b));
}
__device__ __forceinline__ unsigned long long bcast2(float v) {
    unsigned long long r;
    asm("mov.b64 %0, {%1, %1};" : "=l"(r) : "f"(v));
    return r;
}
__device__ __forceinline__ float2 unpack2(unsigned long long v) {
    float2 f;
    asm("mov.b64 {%0, %1}, %2;" : "=f"(f.x), "=f"(f.y) : "l"(v));
    return f;
}

// ---------------------------------------------------------------------------
// Kernel 1: bilinear flow-warp of nbr -> g_warp
// ---------------------------------------------------------------------------
__global__ __launch_bounds__(256) void warp_kernel(const float* __restrict__ nbr,
                                                   const float* __restrict__ flow) {
    int p = blockIdx.x * 256 + threadIdx.x;
    if (p >= B_*HW) return;
    int b = p / HW, s = p % HW;
    int y = s / Ww, x = s % Ww;

    float fx = flow[((size_t)b*2+0)*HW + s];
    float fy = flow[((size_t)b*2+1)*HW + s];
    float py = (float)y + fy, px = (float)x + fx;
    float y0f = floorf(py), x0f = floorf(px);
    float wy = py - y0f, wx = px - x0f;
    int iy0 = (int)y0f, ix0 = (int)x0f;
    int iy1 = iy0 + 1,  ix1 = ix0 + 1;
    bool vy0 = (unsigned)iy0 < Hh, vy1 = (unsigned)iy1 < Hh;
    bool vx0 = (unsigned)ix0 < Ww, vx1 = (unsigned)ix1 < Ww;
    float w00 = (1.f-wy)*(1.f-wx) * (vy0&&vx0 ? 1.f : 0.f);
    float w01 = (1.f-wy)*wx       * (vy0&&vx1 ? 1.f : 0.f);
    float w10 = wy*(1.f-wx)       * (vy1&&vx0 ? 1.f : 0.f);
    float w11 = wy*wx             * (vy1&&vx1 ? 1.f : 0.f);
    int cy0 = min(max(iy0,0),Hh-1), cy1 = min(max(iy1,0),Hh-1);
    int cx0 = min(max(ix0,0),Ww-1), cx1 = min(max(ix1,0),Ww-1);
    int i00 = cy0*Ww+cx0, i01 = cy0*Ww+cx1, i10 = cy1*Ww+cx0, i11 = cy1*Ww+cx1;

    const float* base = nbr + (size_t)b*NFC*HW;
    float* dst = g_warp + (size_t)b*NFC*HW + s;
    #pragma unroll 4
    for (int c = 0; c < NFC; c++) {
        const float* src = base + (size_t)c*HW;
        dst[(size_t)c*HW] = w00*src[i00] + w01*src[i01] + w10*src[i10] + w11*src[i11];
    }
}

// ---------------------------------------------------------------------------
// Kernel 2: conv1 3x3, cin=128 (concat[g_warp, ref]) -> 64, +bias, ReLU -> g_fea
// ---------------------------------------------------------------------------
__global__ __launch_bounds__(256) void conv1_kernel(const float* __restrict__ ref,
                                                    const float* __restrict__ w,
                                                    const float* __restrict__ bias) {
    __shared__ __align__(16) float sw[8][9][NFC];   // 18 KB
    int tid = threadIdx.x;
    int p = blockIdx.x * 256 + tid;
    int b = p / HW, s = p % HW;
    int y = s / Ww, x = s % Ww;

    unsigned long long acc2[NFC/2];
    #pragma unroll
    for (int j = 0; j < NFC/2; j++) acc2[j] = 0ULL;

    #pragma unroll 1
    for (int c0 = 0; c0 < C1_CIN; c0 += 8) {
        __syncthreads();
        for (int i = tid; i < 8*9*NFC; i += 256) {
            int cc = i / (9*NFC); int r = i % (9*NFC);
            int tap = r / NFC;    int o = r % NFC;
            sw[cc][tap][o] = w[((size_t)o*C1_CIN + (c0+cc))*9 + tap];
        }
        __syncthreads();
        #pragma unroll 1
        for (int cc = 0; cc < 8; cc++) {
            int c = c0 + cc;
            const float* src = (c < NFC) ? (g_warp + ((size_t)b*NFC + c)*HW)
                                         : (ref    + ((size_t)b*NFC + (c-NFC))*HW);
            float t[9];
            #pragma unroll
            for (int ky = 0; ky < 3; ky++) {
                int yy = y + ky - 1;
                bool vy = (unsigned)yy < Hh;
                #pragma unroll
                for (int kx = 0; kx < 3; kx++) {
                    int xx = x + kx - 1;
                    t[ky*3+kx] = (vy && (unsigned)xx < Ww) ? src[yy*Ww + xx] : 0.f;
                }
            }
            #pragma unroll
            for (int tap = 0; tap < 9; tap++) {
                unsigned long long iv2 = bcast2(t[tap]);
                const ulonglong2* swp = (const ulonglong2*)&sw[cc][tap][0];
                #pragma unroll
                for (int j = 0; j < NFC/4; j++) {
                    ulonglong2 wv = swp[j];
                    ffma2(acc2[2*j+0], iv2, wv.x);
                    ffma2(acc2[2*j+1], iv2, wv.y);
                }
            }
        }
    }
    float* dst = g_fea + (size_t)b*NFC*HW + s;
    #pragma unroll
    for (int j = 0; j < NFC/2; j++) {
        float2 v = unpack2(acc2[j]);
        float v0 = v.x + bias[2*j+0];
        float v1 = v.y + bias[2*j+1];
        dst[(size_t)(2*j+0)*HW] = v0 > 0.f ? v0 : 0.f;
        dst[(size_t)(2*j+1)*HW] = v1 > 0.f ? v1 : 0.f;
    }
}

// ---------------------------------------------------------------------------
// Kernel 3: om conv 3x3, cin=66 (concat[g_fea, flow]) -> 216 (72 per z-block)
// ---------------------------------------------------------------------------
__global__ __launch_bounds__(256) void om_kernel(const float* __restrict__ flow,
                                                 const float* __restrict__ w,
                                                 const float* __restrict__ bias) {
    __shared__ __align__(16) float sw[8][9][OM_OUT];  // 20.7 KB
    int tid = threadIdx.x;
    int p = blockIdx.x * 256 + tid;
    int ob = blockIdx.y * OM_OUT;
    int b = p / HW, s = p % HW;
    int y = s / Ww, x = s % Ww;

    unsigned long long acc2[OM_OUT/2];
    #pragma unroll
    for (int j = 0; j < OM_OUT/2; j++) acc2[j] = 0ULL;

    #pragma unroll 1
    for (int c0 = 0; c0 < OM_CIN; c0 += 8) {
        int nc = min(8, OM_CIN - c0);
        __syncthreads();
        for (int i = tid; i < nc*9*OM_OUT; i += 256) {
            int cc = i / (9*OM_OUT); int r = i % (9*OM_OUT);
            int tap = r / OM_OUT;    int o = r % OM_OUT;
            sw[cc][tap][o] = w[((size_t)(ob+o)*OM_CIN + (c0+cc))*9 + tap];
        }
        __syncthreads();
        #pragma unroll 1
        for (int cc = 0; cc < nc; cc++) {
            int c = c0 + cc;
            const float* src = (c < NFC) ? (g_fea + ((size_t)b*NFC + c)*HW)
                                         : (flow  + ((size_t)b*2 + (c-NFC))*HW);
            float t[9];
            #pragma unroll
            for (int ky = 0; ky < 3; ky++) {
                int yy = y + ky - 1;
                bool vy = (unsigned)yy < Hh;
                #pragma unroll
                for (int kx = 0; kx < 3; kx++) {
                    int xx = x + kx - 1;
                    t[ky*3+kx] = (vy && (unsigned)xx < Ww) ? src[yy*Ww + xx] : 0.f;
                }
            }
            #pragma unroll
            for (int tap = 0; tap < 9; tap++) {
                unsigned long long iv2 = bcast2(t[tap]);
                const ulonglong2* swp = (const ulonglong2*)&sw[cc][tap][0];
                #pragma unroll
                for (int j = 0; j < OM_OUT/4; j++) {
                    ulonglong2 wv = swp[j];
                    ffma2(acc2[2*j+0], iv2, wv.x);
                    ffma2(acc2[2*j+1], iv2, wv.y);
                }
            }
        }
    }
    float* dst = g_om + (size_t)b*OMC*HW + (size_t)ob*HW + s;
    #pragma unroll
    for (int j = 0; j < OM_OUT/2; j++) {
        float2 v = unpack2(acc2[j]);
        dst[(size_t)(2*j+0)*HW] = v.x + bias[ob+2*j+0];
        dst[(size_t)(2*j+1)*HW] = v.y + bias[ob+2*j+1];
    }
}

// ---------------------------------------------------------------------------
// Kernel 4: fused DCN — offsets+flow, sigmoid mask, bilinear gather, einsum
// ---------------------------------------------------------------------------
__global__ __launch_bounds__(256) void dcn_kernel(const float* __restrict__ nbr,
                                                  const float* __restrict__ flow,
                                                  const float* __restrict__ w,
                                                  const float* __restrict__ bias,
                                                  float* __restrict__ out) {
    __shared__ __align__(16) float sw[KK][CGC][NFC];  // 18 KB
    int tid = threadIdx.x;
    int p = blockIdx.x * 256 + tid;
    int b = p / HW, s = p % HW;
    int y = s / Ww, x = s % Ww;

    float fx = flow[((size_t)b*2+0)*HW + s];
    float fy = flow[((size_t)b*2+1)*HW + s];

    unsigned long long acc2[NFC/2];
    #pragma unroll
    for (int j = 0; j < NFC/2; j++) acc2[j] = 0ULL;

    const float* omb = g_om + (size_t)b*OMC*HW + s;

    #pragma unroll 1
    for (int g = 0; g < DGC; g++) {
        __syncthreads();
        for (int i = tid; i < KK*CGC*NFC; i += 256) {
            int k = i / (CGC*NFC); int r = i % (CGC*NFC);
            int cg = r / NFC;      int o = r % NFC;
            sw[k][cg][o] = w[((size_t)o*NFC + (g*CGC+cg))*9 + k];
        }
        __syncthreads();

        const float* base = nbr + ((size_t)b*NFC + g*CGC)*HW;
        #pragma unroll 1
        for (int k = 0; k < KK; k++) {
            int ky = k / 3, kx = k % 3;
            float dy = omb[(size_t)(18*g + 2*k    )*HW];
            float dx = omb[(size_t)(18*g + 2*k + 1)*HW];
            float mv = omb[(size_t)(144 + 9*g + k )*HW];
            float m  = 1.f / (1.f + expf(-mv));

            float spy = (float)(y - 1 + ky) + dy + fy;
            float spx = (float)(x - 1 + kx) + dx + fx;
            float y0f = floorf(spy), x0f = floorf(spx);
            float wy = spy - y0f, wx = spx - x0f;
            int iy0 = (int)y0f, ix0 = (int)x0f;
            int iy1 = iy0 + 1,  ix1 = ix0 + 1;
            bool vy0 = (unsigned)iy0 < Hh, vy1 = (unsigned)iy1 < Hh;
            bool vx0 = (unsigned)ix0 < Ww, vx1 = (unsigned)ix1 < Ww;
            float w00 = m*(1.f-wy)*(1.f-wx) * (vy0&&vx0 ? 1.f : 0.f);
            float w01 = m*(1.f-wy)*wx       * (vy0&&vx1 ? 1.f : 0.f);
            float w10 = m*wy*(1.f-wx)       * (vy1&&vx0 ? 1.f : 0.f);
            float w11 = m*wy*wx             * (vy1&&vx1 ? 1.f : 0.f);
            int cy0 = min(max(iy0,0),Hh-1), cy1 = min(max(iy1,0),Hh-1);
            int cx0 = min(max(ix0,0),Ww-1), cx1 = min(max(ix1,0),Ww-1);
            int i00 = cy0*Ww+cx0, i01 = cy0*Ww+cx1, i10 = cy1*Ww+cx0, i11 = cy1*Ww+cx1;

            float v[CGC];
            #pragma unroll
            for (int cg = 0; cg < CGC; cg++) {
                const float* src = base + (size_t)cg*HW;
                v[cg] = w00*src[i00] + w01*src[i01] + w10*src[i10] + w11*src[i11];
            }
            #pragma unroll
            for (int cg = 0; cg < CGC; cg++) {
                unsigned long long iv2 = bcast2(v[cg]);
                const ulonglong2* swp = (const ulonglong2*)&sw[k][cg][0];
                #pragma unroll
                for (int j = 0; j < NFC/4; j++) {
                    ulonglong2 wv = swp[j];
                    ffma2(acc2[2*j+0], iv2, wv.x);
                    ffma2(acc2[2*j+1], iv2, wv.y);
                }
            }
        }
    }
    float* dst = out + (size_t)b*NFC*HW + s;
    #pragma unroll
    for (int j = 0; j < NFC/2; j++) {
        float2 v = unpack2(acc2[j]);
        dst[(size_t)(2*j+0)*HW] = v.x + bias[2*j+0];
        dst[(size_t)(2*j+1)*HW] = v.y + bias[2*j+1];
    }
}

// ---------------------------------------------------------------------------
extern "C" void kernel_launch(void* const* d_in, const int* in_sizes, int n_in,
                              void* d_out, int out_size) {
    const float* nbr  = (const float*)d_in[0];
    const float* ref  = (const float*)d_in[1];
    const float* flow = (const float*)d_in[2];
    const float* c1w  = (const float*)d_in[3];
    const float* c1b  = (const float*)d_in[4];
    const float* omw  = (const float*)d_in[5];
    const float* ombi = (const float*)d_in[6];
    const float* dw   = (const float*)d_in[7];
    const float* db   = (const float*)d_in[8];
    float* out = (float*)d_out;

    int nblk = (B_*HW) / 256;   // 512
    warp_kernel <<<nblk, 256>>>(nbr, flow);
    conv1_kernel<<<nblk, 256>>>(ref, c1w, c1b);
    om_kernel   <<<dim3(nblk, 3), 256>>>(flow, omw, ombi);
    dcn_kernel  <<<nblk, 256>>>(nbr, flow, dw, db, out);
}

// round 6
// speedup vs baseline: 1.4441x; 1.4441x over previous
#include <cuda_runtime.h>
#include <math.h>

#define B_  2
#define NFC 64
#define Hh  256
#define Ww  256
#define HW  (Hh*Ww)
#define DGC 8
#define CGC 8
#define KK  9
#define OMC 216
#define OM_CIN 66
#define OM_CHUNK 36
#define C1_CIN 128

// Scratch (static device arrays; no runtime allocation)
__device__ float g_warp[(size_t)B_*NFC*HW];   // 33.5 MB
__device__ float g_fea [(size_t)B_*NFC*HW];   // 33.5 MB
__device__ float g_om  [(size_t)B_*OMC*HW];   // 113 MB

// ---- packed f32x2 helpers (Blackwell full-rate fp32 path) ---------------
__device__ __forceinline__ void ffma2(unsigned long long& acc,
                                      unsigned long long a,
                                      unsigned long long b) {
    asm("fma.rn.f32x2 %0, %1, %2, %0;" : "+l"(acc) : "l"(a), "l"(b));
}
__device__ __forceinline__ unsigned long long bcast2(float v) {
    unsigned long long r;
    asm("mov.b64 %0, {%1, %1};" : "=l"(r) : "f"(v));
    return r;
}
__device__ __forceinline__ float2 unpack2(unsigned long long v) {
    float2 f;
    asm("mov.b64 {%0, %1}, %2;" : "=f"(f.x), "=f"(f.y) : "l"(v));
    return f;
}

// ---------------------------------------------------------------------------
// Kernel 1: bilinear flow-warp of nbr -> g_warp   (HBM-bound, unchanged)
// ---------------------------------------------------------------------------
__global__ __launch_bounds__(256) void warp_kernel(const float* __restrict__ nbr,
                                                   const float* __restrict__ flow) {
    int p = blockIdx.x * 256 + threadIdx.x;
    if (p >= B_*HW) return;
    int b = p / HW, s = p % HW;
    int y = s / Ww, x = s % Ww;

    float fx = flow[((size_t)b*2+0)*HW + s];
    float fy = flow[((size_t)b*2+1)*HW + s];
    float py = (float)y + fy, px = (float)x + fx;
    float y0f = floorf(py), x0f = floorf(px);
    float wy = py - y0f, wx = px - x0f;
    int iy0 = (int)y0f, ix0 = (int)x0f;
    int iy1 = iy0 + 1,  ix1 = ix0 + 1;
    bool vy0 = (unsigned)iy0 < Hh, vy1 = (unsigned)iy1 < Hh;
    bool vx0 = (unsigned)ix0 < Ww, vx1 = (unsigned)ix1 < Ww;
    float w00 = (1.f-wy)*(1.f-wx) * (vy0&&vx0 ? 1.f : 0.f);
    float w01 = (1.f-wy)*wx       * (vy0&&vx1 ? 1.f : 0.f);
    float w10 = wy*(1.f-wx)       * (vy1&&vx0 ? 1.f : 0.f);
    float w11 = wy*wx             * (vy1&&vx1 ? 1.f : 0.f);
    int cy0 = min(max(iy0,0),Hh-1), cy1 = min(max(iy1,0),Hh-1);
    int cx0 = min(max(ix0,0),Ww-1), cx1 = min(max(ix1,0),Ww-1);
    int i00 = cy0*Ww+cx0, i01 = cy0*Ww+cx1, i10 = cy1*Ww+cx0, i11 = cy1*Ww+cx1;

    const float* base = nbr + (size_t)b*NFC*HW;
    float* dst = g_warp + (size_t)b*NFC*HW + s;
    #pragma unroll 4
    for (int c = 0; c < NFC; c++) {
        const float* src = base + (size_t)c*HW;
        dst[(size_t)c*HW] = w00*src[i00] + w01*src[i01] + w10*src[i10] + w11*src[i11];
    }
}

// ---------------------------------------------------------------------------
// Kernel 2: conv1 3x3, cin=128 -> 64, ReLU.  128 thr/block, 2 px/thread (1 row)
// ---------------------------------------------------------------------------
__global__ __launch_bounds__(128) void conv1_kernel(const float* __restrict__ ref,
                                                    const float* __restrict__ w,
                                                    const float* __restrict__ bias) {
    __shared__ __align__(16) float sw[8][9][NFC];   // 18 KB
    int tid = threadIdx.x;
    int row = blockIdx.x;              // 0..511 = b*Hh + y
    int b = row / Hh, y = row % Hh;
    int xA = tid, xB = tid + 128;
    int sA = y*Ww + xA, sB = sA + 128;

    unsigned long long accA[NFC/2], accB[NFC/2];
    #pragma unroll
    for (int j = 0; j < NFC/2; j++) { accA[j] = 0ULL; accB[j] = 0ULL; }

    #pragma unroll 1
    for (int c0 = 0; c0 < C1_CIN; c0 += 8) {
        __syncthreads();
        for (int i = tid; i < 8*9*NFC; i += 128) {
            int cc = i / (9*NFC); int r = i % (9*NFC);
            int tap = r / NFC;    int o = r % NFC;
            sw[cc][tap][o] = w[((size_t)o*C1_CIN + (c0+cc))*9 + tap];
        }
        __syncthreads();
        #pragma unroll 1
        for (int cc = 0; cc < 8; cc++) {
            int c = c0 + cc;
            const float* src = (c < NFC) ? (g_warp + ((size_t)b*NFC + c)*HW)
                                         : (ref    + ((size_t)b*NFC + (c-NFC))*HW);
            float tA[9], tB[9];
            #pragma unroll
            for (int ky = 0; ky < 3; ky++) {
                int yy = y + ky - 1;
                bool vy = (unsigned)yy < Hh;
                const float* srow = src + yy*Ww;
                #pragma unroll
                for (int kx = 0; kx < 3; kx++) {
                    int x1 = xA + kx - 1, x2 = xB + kx - 1;
                    tA[ky*3+kx] = (vy && (unsigned)x1 < Ww) ? srow[x1] : 0.f;
                    tB[ky*3+kx] = (vy && (unsigned)x2 < Ww) ? srow[x2] : 0.f;
                }
            }
            #pragma unroll
            for (int tap = 0; tap < 9; tap++) {
                unsigned long long ivA = bcast2(tA[tap]);
                unsigned long long ivB = bcast2(tB[tap]);
                const ulonglong2* swp = (const ulonglong2*)&sw[cc][tap][0];
                #pragma unroll
                for (int j = 0; j < NFC/4; j++) {
                    ulonglong2 wv = swp[j];
                    ffma2(accA[2*j+0], ivA, wv.x);
                    ffma2(accA[2*j+1], ivA, wv.y);
                    ffma2(accB[2*j+0], ivB, wv.x);
                    ffma2(accB[2*j+1], ivB, wv.y);
                }
            }
        }
    }
    float* dstA = g_fea + (size_t)b*NFC*HW + sA;
    float* dstB = g_fea + (size_t)b*NFC*HW + sB;
    #pragma unroll
    for (int j = 0; j < NFC/2; j++) {
        float2 vA = unpack2(accA[j]);
        float2 vB = unpack2(accB[j]);
        float b0 = bias[2*j+0], b1 = bias[2*j+1];
        float a0 = vA.x + b0, a1 = vA.y + b1;
        float c0v = vB.x + b0, c1v = vB.y + b1;
        dstA[(size_t)(2*j+0)*HW] = a0 > 0.f ? a0 : 0.f;
        dstA[(size_t)(2*j+1)*HW] = a1 > 0.f ? a1 : 0.f;
        dstB[(size_t)(2*j+0)*HW] = c0v > 0.f ? c0v : 0.f;
        dstB[(size_t)(2*j+1)*HW] = c1v > 0.f ? c1v : 0.f;
    }
}

// ---------------------------------------------------------------------------
// Kernel 3: om conv 3x3, cin=66 -> 216. 128 thr, 2 px/thread, 36 outs per z.
// ---------------------------------------------------------------------------
__global__ __launch_bounds__(128) void om_kernel(const float* __restrict__ flow,
                                                 const float* __restrict__ w,
                                                 const float* __restrict__ bias) {
    __shared__ __align__(16) float sw[8][9][OM_CHUNK];  // 10.4 KB
    int tid = threadIdx.x;
    int row = blockIdx.x;
    int ob = blockIdx.y * OM_CHUNK;
    int b = row / Hh, y = row % Hh;
    int xA = tid, xB = tid + 128;
    int sA = y*Ww + xA, sB = sA + 128;

    unsigned long long accA[OM_CHUNK/2], accB[OM_CHUNK/2];
    #pragma unroll
    for (int j = 0; j < OM_CHUNK/2; j++) { accA[j] = 0ULL; accB[j] = 0ULL; }

    #pragma unroll 1
    for (int c0 = 0; c0 < OM_CIN; c0 += 8) {
        int nc = min(8, OM_CIN - c0);
        __syncthreads();
        for (int i = tid; i < nc*9*OM_CHUNK; i += 128) {
            int cc = i / (9*OM_CHUNK); int r = i % (9*OM_CHUNK);
            int tap = r / OM_CHUNK;    int o = r % OM_CHUNK;
            sw[cc][tap][o] = w[((size_t)(ob+o)*OM_CIN + (c0+cc))*9 + tap];
        }
        __syncthreads();
        #pragma unroll 1
        for (int cc = 0; cc < nc; cc++) {
            int c = c0 + cc;
            const float* src = (c < NFC) ? (g_fea + ((size_t)b*NFC + c)*HW)
                                         : (flow  + ((size_t)b*2 + (c-NFC))*HW);
            float tA[9], tB[9];
            #pragma unroll
            for (int ky = 0; ky < 3; ky++) {
                int yy = y + ky - 1;
                bool vy = (unsigned)yy < Hh;
                const float* srow = src + yy*Ww;
                #pragma unroll
                for (int kx = 0; kx < 3; kx++) {
                    int x1 = xA + kx - 1, x2 = xB + kx - 1;
                    tA[ky*3+kx] = (vy && (unsigned)x1 < Ww) ? srow[x1] : 0.f;
                    tB[ky*3+kx] = (vy && (unsigned)x2 < Ww) ? srow[x2] : 0.f;
                }
            }
            #pragma unroll
            for (int tap = 0; tap < 9; tap++) {
                unsigned long long ivA = bcast2(tA[tap]);
                unsigned long long ivB = bcast2(tB[tap]);
                const ulonglong2* swp = (const ulonglong2*)&sw[cc][tap][0];
                #pragma unroll
                for (int j = 0; j < OM_CHUNK/4; j++) {
                    ulonglong2 wv = swp[j];
                    ffma2(accA[2*j+0], ivA, wv.x);
                    ffma2(accA[2*j+1], ivA, wv.y);
                    ffma2(accB[2*j+0], ivB, wv.x);
                    ffma2(accB[2*j+1], ivB, wv.y);
                }
            }
        }
    }
    float* dstA = g_om + (size_t)b*OMC*HW + (size_t)ob*HW + sA;
    float* dstB = g_om + (size_t)b*OMC*HW + (size_t)ob*HW + sB;
    #pragma unroll
    for (int j = 0; j < OM_CHUNK/2; j++) {
        float2 vA = unpack2(accA[j]);
        float2 vB = unpack2(accB[j]);
        float b0 = bias[ob+2*j+0], b1 = bias[ob+2*j+1];
        dstA[(size_t)(2*j+0)*HW] = vA.x + b0;
        dstA[(size_t)(2*j+1)*HW] = vA.y + b1;
        dstB[(size_t)(2*j+0)*HW] = vB.x + b0;
        dstB[(size_t)(2*j+1)*HW] = vB.y + b1;
    }
}

// ---------------------------------------------------------------------------
// Kernel 4: fused DCN. 128 thr/block, 2 px/thread (1 row).
// ---------------------------------------------------------------------------
__global__ __launch_bounds__(128) void dcn_kernel(const float* __restrict__ nbr,
                                                  const float* __restrict__ flow,
                                                  const float* __restrict__ w,
                                                  const float* __restrict__ bias,
                                                  float* __restrict__ out) {
    __shared__ __align__(16) float sw[KK][CGC][NFC];  // 18 KB
    int tid = threadIdx.x;
    int row = blockIdx.x;
    int b = row / Hh, y = row % Hh;
    int xA = tid, xB = tid + 128;
    int sA = y*Ww + xA, sB = sA + 128;

    float fxA = flow[((size_t)b*2+0)*HW + sA];
    float fyA = flow[((size_t)b*2+1)*HW + sA];
    float fxB = flow[((size_t)b*2+0)*HW + sB];
    float fyB = flow[((size_t)b*2+1)*HW + sB];

    unsigned long long accA[NFC/2], accB[NFC/2];
    #pragma unroll
    for (int j = 0; j < NFC/2; j++) { accA[j] = 0ULL; accB[j] = 0ULL; }

    const float* ombA = g_om + (size_t)b*OMC*HW + sA;
    const float* ombB = g_om + (size_t)b*OMC*HW + sB;

    #pragma unroll 1
    for (int g = 0; g < DGC; g++) {
        __syncthreads();
        for (int i = tid; i < KK*CGC*NFC; i += 128) {
            int k = i / (CGC*NFC); int r = i % (CGC*NFC);
            int cg = r / NFC;      int o = r % NFC;
            sw[k][cg][o] = w[((size_t)o*NFC + (g*CGC+cg))*9 + k];
        }
        __syncthreads();

        const float* base = nbr + ((size_t)b*NFC + g*CGC)*HW;
        #pragma unroll 1
        for (int k = 0; k < KK; k++) {
            int ky = k / 3, kx = k % 3;
            // --- pixel A sampling setup ---
            float dyA = ombA[(size_t)(18*g + 2*k    )*HW];
            float dxA = ombA[(size_t)(18*g + 2*k + 1)*HW];
            float mvA = ombA[(size_t)(144 + 9*g + k )*HW];
            float dyB = ombB[(size_t)(18*g + 2*k    )*HW];
            float dxB = ombB[(size_t)(18*g + 2*k + 1)*HW];
            float mvB = ombB[(size_t)(144 + 9*g + k )*HW];
            float mA = 1.f / (1.f + expf(-mvA));
            float mB = 1.f / (1.f + expf(-mvB));

            float spyA = (float)(y - 1 + ky) + dyA + fyA;
            float spxA = (float)(xA - 1 + kx) + dxA + fxA;
            float spyB = (float)(y - 1 + ky) + dyB + fyB;
            float spxB = (float)(xB - 1 + kx) + dxB + fxB;

            float y0fA = floorf(spyA), x0fA = floorf(spxA);
            float wyA = spyA - y0fA, wxA = spxA - x0fA;
            int iy0A = (int)y0fA, ix0A = (int)x0fA;
            int iy1A = iy0A + 1,  ix1A = ix0A + 1;
            bool vy0A = (unsigned)iy0A < Hh, vy1A = (unsigned)iy1A < Hh;
            bool vx0A = (unsigned)ix0A < Ww, vx1A = (unsigned)ix1A < Ww;
            float w00A = mA*(1.f-wyA)*(1.f-wxA) * (vy0A&&vx0A ? 1.f : 0.f);
            float w01A = mA*(1.f-wyA)*wxA       * (vy0A&&vx1A ? 1.f : 0.f);
            float w10A = mA*wyA*(1.f-wxA)       * (vy1A&&vx0A ? 1.f : 0.f);
            float w11A = mA*wyA*wxA             * (vy1A&&vx1A ? 1.f : 0.f);
            int cy0A = min(max(iy0A,0),Hh-1), cy1A = min(max(iy1A,0),Hh-1);
            int cx0A = min(max(ix0A,0),Ww-1), cx1A = min(max(ix1A,0),Ww-1);
            int i00A = cy0A*Ww+cx0A, i01A = cy0A*Ww+cx1A;
            int i10A = cy1A*Ww+cx0A, i11A = cy1A*Ww+cx1A;

            float y0fB = floorf(spyB), x0fB = floorf(spxB);
            float wyB = spyB - y0fB, wxB = spxB - x0fB;
            int iy0B = (int)y0fB, ix0B = (int)x0fB;
            int iy1B = iy0B + 1,  ix1B = ix0B + 1;
            bool vy0B = (unsigned)iy0B < Hh, vy1B = (unsigned)iy1B < Hh;
            bool vx0B = (unsigned)ix0B < Ww, vx1B = (unsigned)ix1B < Ww;
            float w00B = mB*(1.f-wyB)*(1.f-wxB) * (vy0B&&vx0B ? 1.f : 0.f);
            float w01B = mB*(1.f-wyB)*wxB       * (vy0B&&vx1B ? 1.f : 0.f);
            float w10B = mB*wyB*(1.f-wxB)       * (vy1B&&vx0B ? 1.f : 0.f);
            float w11B = mB*wyB*wxB             * (vy1B&&vx1B ? 1.f : 0.f);
            int cy0B = min(max(iy0B,0),Hh-1), cy1B = min(max(iy1B,0),Hh-1);
            int cx0B = min(max(ix0B,0),Ww-1), cx1B = min(max(ix1B,0),Ww-1);
            int i00B = cy0B*Ww+cx0B, i01B = cy0B*Ww+cx1B;
            int i10B = cy1B*Ww+cx0B, i11B = cy1B*Ww+cx1B;

            float vA[CGC], vB[CGC];
            #pragma unroll
            for (int cg = 0; cg < CGC; cg++) {
                const float* src = base + (size_t)cg*HW;
                vA[cg] = w00A*src[i00A] + w01A*src[i01A] + w10A*src[i10A] + w11A*src[i11A];
                vB[cg] = w00B*src[i00B] + w01B*src[i01B] + w10B*src[i10B] + w11B*src[i11B];
            }
            #pragma unroll
            for (int cg = 0; cg < CGC; cg++) {
                unsigned long long ivA = bcast2(vA[cg]);
                unsigned long long ivB = bcast2(vB[cg]);
                const ulonglong2* swp = (const ulonglong2*)&sw[k][cg][0];
                #pragma unroll
                for (int j = 0; j < NFC/4; j++) {
                    ulonglong2 wv = swp[j];
                    ffma2(accA[2*j+0], ivA, wv.x);
                    ffma2(accA[2*j+1], ivA, wv.y);
                    ffma2(accB[2*j+0], ivB, wv.x);
                    ffma2(accB[2*j+1], ivB, wv.y);
                }
            }
        }
    }
    float* dstA = out + (size_t)b*NFC*HW + sA;
    float* dstB = out + (size_t)b*NFC*HW + sB;
    #pragma unroll
    for (int j = 0; j < NFC/2; j++) {
        float2 vA = unpack2(accA[j]);
        float2 vB = unpack2(accB[j]);
        float b0 = bias[2*j+0], b1 = bias[2*j+1];
        dstA[(size_t)(2*j+0)*HW] = vA.x + b0;
        dstA[(size_t)(2*j+1)*HW] = vA.y + b1;
        dstB[(size_t)(2*j+0)*HW] = vB.x + b0;
        dstB[(size_t)(2*j+1)*HW] = vB.y + b1;
    }
}

// ---------------------------------------------------------------------------
extern "C" void kernel_launch(void* const* d_in, const int* in_sizes, int n_in,
                              void* d_out, int out_size) {
    const float* nbr  = (const float*)d_in[0];
    const float* ref  = (const float*)d_in[1];
    const float* flow = (const float*)d_in[2];
    const float* c1w  = (const float*)d_in[3];
    const float* c1b  = (const float*)d_in[4];
    const float* omw  = (const float*)d_in[5];
    const float* ombi = (const float*)d_in[6];
    const float* dw   = (const float*)d_in[7];
    const float* db   = (const float*)d_in[8];
    float* out = (float*)d_out;

    int nrows = B_ * Hh;                 // 512 row-blocks
    warp_kernel <<<(B_*HW)/256, 256>>>(nbr, flow);
    conv1_kernel<<<nrows, 128>>>(ref, c1w, c1b);
    om_kernel   <<<dim3(nrows, OMC/OM_CHUNK), 128>>>(flow, omw, ombi);
    dcn_kernel  <<<nrows, 128>>>(nbr, flow, dw, db, out);
}